// round 10
// baseline (speedup 1.0000x reference)
#include <cuda_runtime.h>
#include <cuda_bf16.h>
#include <cstdint>

// N=50000 nodes, E=800000 edges, IN_DIM=256, HEADS=4, HID=64 -> out 256.
#define MAXN 50000
#define MAXE 800000
#define MAXT (MAXE + MAXN)
#define DIM 256
#define NEG_SLOPE 0.2f

// ------------------------- device scratch -------------------------
__device__ float          g_h[(size_t)MAXN * DIM];     // projected features fp32
__device__ __nv_bfloat16  g_xhi[(size_t)MAXN * DIM];   // x split hi
__device__ __nv_bfloat16  g_xlo[(size_t)MAXN * DIM];   // x split lo
__device__ __nv_bfloat16  g_wthi[DIM * DIM];           // W^T split hi: [n][k]
__device__ __nv_bfloat16  g_wtlo[DIM * DIM];
__device__ float4 g_asrc[MAXN];
__device__ float4 g_adst[MAXN];
__device__ float4 g_denom[MAXN];
__device__ float4 g_num[MAXT];
__device__ int    g_deg[MAXN];
__device__ int    g_rowoff[MAXN];
__device__ int    g_cursor[MAXN];
__device__ int2   g_slot[MAXT];        // {src, edge_id} binned by dst
__device__ int    g_bsum[64];
__device__ int    g_bbase[64];
__device__ int    g_idx_stride;        // 1 = int32 indices, 2 = int64 low word

// ------------------------- helpers -------------------------
__device__ __forceinline__ uint32_t smem_u32(const void* p) {
    uint32_t a;
    asm("{ .reg .u64 t; cvta.to.shared.u64 t, %1; cvt.u32.u64 %0, t; }"
        : "=r"(a) : "l"(p));
    return a;
}
__device__ __forceinline__ void red_add_v4(float4* addr, float4 v) {
    asm volatile("red.global.add.v4.f32 [%0], {%1,%2,%3,%4};"
                 :: "l"(addr), "f"(v.x), "f"(v.y), "f"(v.z), "f"(v.w) : "memory");
}

// ------------------------- 0) dtype detection -------------------------
// JAX default x64-off silently makes edge_index int32; detect via odd words.
__global__ void detect_idx_kernel(const int* __restrict__ ei32, int E)
{
    __shared__ int s_nonzero;
    if (threadIdx.x == 0) s_nonzero = 0;
    __syncthreads();
    int nz = 0;
    int samples = (E < 4096) ? E : 4096;
    for (int i = threadIdx.x; i < samples; i += blockDim.x)
        nz |= ei32[2 * i + 1];
    if (nz) atomicOr(&s_nonzero, 1);
    __syncthreads();
    if (threadIdx.x == 0) g_idx_stride = s_nonzero ? 1 : 2;
}

__device__ __forceinline__ void load_edge(const int* __restrict__ ei32,
                                          int t, int E, int stride, int& s, int& d)
{
    s = ei32[(size_t)t * stride];
    d = ei32[((size_t)E + t) * stride];
}

// ------------------------- 1a) W transpose + bf16 split -------------------------
__global__ void prep_w_kernel(const float* __restrict__ W)
{
    int i = blockIdx.x * blockDim.x + threadIdx.x;   // i = k*256 + n
    if (i < DIM * DIM) {
        int k = i >> 8, n = i & 255;
        float w = W[i];
        __nv_bfloat16 hi = __float2bfloat16(w);
        __nv_bfloat16 lo = __float2bfloat16(w - __bfloat162float(hi));
        g_wthi[n * DIM + k] = hi;
        g_wtlo[n * DIM + k] = lo;
    }
}

// ------------------------- 1b) x bf16 split -------------------------
__global__ void split_x_kernel(const float* __restrict__ x, int total4)
{
    int i = blockIdx.x * blockDim.x + threadIdx.x;
    if (i < total4) {
        float4 v = ((const float4*)x)[i];
        __nv_bfloat16 h0 = __float2bfloat16(v.x), h1 = __float2bfloat16(v.y);
        __nv_bfloat16 h2 = __float2bfloat16(v.z), h3 = __float2bfloat16(v.w);
        __nv_bfloat16 l0 = __float2bfloat16(v.x - __bfloat162float(h0));
        __nv_bfloat16 l1 = __float2bfloat16(v.y - __bfloat162float(h1));
        __nv_bfloat16 l2 = __float2bfloat16(v.z - __bfloat162float(h2));
        __nv_bfloat16 l3 = __float2bfloat16(v.w - __bfloat162float(h3));
        ((__nv_bfloat162*)g_xhi)[2 * i]     = __halves2bfloat162(h0, h1);
        ((__nv_bfloat162*)g_xhi)[2 * i + 1] = __halves2bfloat162(h2, h3);
        ((__nv_bfloat162*)g_xlo)[2 * i]     = __halves2bfloat162(l0, l1);
        ((__nv_bfloat162*)g_xlo)[2 * i + 1] = __halves2bfloat162(l2, l3);
    }
}

// ------------------------- 2) init: denom=0, deg=0 -------------------------
__global__ void init2_kernel(int N)
{
    int i = blockIdx.x * blockDim.x + threadIdx.x;
    if (i < N) { g_denom[i] = make_float4(0.f, 0.f, 0.f, 0.f); g_deg[i] = 0; }
}

// ------------------------- 3) GEMM via mma.sync bf16x3 -------------------------
// h = x@W with error-free-ish split: hi*hi + lo*hi + hi*lo, fp32 accumulate.
// NOTE: tcgen05 is compile-blocked (harness lowers via compute_103 PTX, no 'a'
// feature), so we use baseline-PTX HMMA mma.sync.m16n8k16.
// CTA tile 64(M) x 256(N), BK=64, 8 warps (2x4), warp tile 32x64.
#define GBM 64
#define GBK 64
#define ASTR 72   // bf16 stride with +8 pad -> ldmatrix conflict-free

__global__ __launch_bounds__(256)
void gemm_mma_kernel(int M)
{
    __shared__ __align__(16) __nv_bfloat16 As[GBM * ASTR];   //  9216 B
    __shared__ __align__(16) __nv_bfloat16 Bs[DIM * ASTR];   // 36864 B

    int tid = threadIdx.x, lane = tid & 31, wid = tid >> 5;
    int warp_m = wid & 1;        // 0..1
    int warp_n = wid >> 1;       // 0..3
    int brow = blockIdx.x * GBM;

    float acc[2][8][4];
    #pragma unroll
    for (int mi = 0; mi < 2; mi++)
        #pragma unroll
        for (int ni = 0; ni < 8; ni++)
            #pragma unroll
            for (int q = 0; q < 4; q++) acc[mi][ni][q] = 0.f;

    uint32_t As_a = smem_u32(As);
    uint32_t Bs_a = smem_u32(Bs);

    // ldmatrix lane address components
    int a_row = warp_m * 32 + (lane & 15);      // + mi*16
    int a_k   = (lane >> 4) << 3;               // 0 or 8, + ks*16
    int b_row = warp_n * 64 + (lane & 7);       // + ni*8
    int b_k   = ((lane >> 3) & 1) << 3;         // 0 or 8, + ks*16

    for (int it = 0; it < 12; it++) {
        int pass = it >> 2, kc = it & 3;
        const __nv_bfloat16* ap = (pass == 1) ? g_xlo  : g_xhi;
        const __nv_bfloat16* bp = (pass == 2) ? g_wtlo : g_wthi;

        __syncthreads();   // previous iter's reads done
        // A: 64 rows x 64 bf16 = 512 uint4, 2 per thread
        #pragma unroll
        for (int i = 0; i < 2; i++) {
            int idx = tid + i * 256;
            int r = idx >> 3, c = (idx & 7) << 3;
            uint4 v = make_uint4(0u, 0u, 0u, 0u);
            if (brow + r < M)
                v = *(const uint4*)(ap + (size_t)(brow + r) * DIM + kc * GBK + c);
            *(uint4*)&As[r * ASTR + c] = v;
        }
        // B: 256 rows x 64 bf16 = 2048 uint4, 8 per thread
        #pragma unroll
        for (int i = 0; i < 8; i++) {
            int idx = tid + i * 256;
            int r = idx >> 3, c = (idx & 7) << 3;
            uint4 v = *(const uint4*)(bp + (size_t)r * DIM + kc * GBK + c);
            *(uint4*)&Bs[r * ASTR + c] = v;
        }
        __syncthreads();

        #pragma unroll
        for (int ks = 0; ks < 4; ks++) {
            uint32_t a_frag[2][4];
            #pragma unroll
            for (int mi = 0; mi < 2; mi++) {
                uint32_t addr = As_a +
                    (uint32_t)(((a_row + mi * 16) * ASTR + ks * 16 + a_k) * 2);
                asm volatile(
                    "ldmatrix.sync.aligned.m8n8.x4.shared.b16 {%0,%1,%2,%3}, [%4];"
                    : "=r"(a_frag[mi][0]), "=r"(a_frag[mi][1]),
                      "=r"(a_frag[mi][2]), "=r"(a_frag[mi][3])
                    : "r"(addr));
            }
            #pragma unroll
            for (int ni = 0; ni < 8; ni++) {
                uint32_t b0, b1;
                uint32_t addr = Bs_a +
                    (uint32_t)(((b_row + ni * 8) * ASTR + ks * 16 + b_k) * 2);
                asm volatile(
                    "ldmatrix.sync.aligned.m8n8.x2.shared.b16 {%0,%1}, [%2];"
                    : "=r"(b0), "=r"(b1) : "r"(addr));
                #pragma unroll
                for (int mi = 0; mi < 2; mi++) {
                    asm volatile(
                        "mma.sync.aligned.m16n8k16.row.col.f32.bf16.bf16.f32 "
                        "{%0,%1,%2,%3}, {%4,%5,%6,%7}, {%8,%9}, {%0,%1,%2,%3};"
                        : "+f"(acc[mi][ni][0]), "+f"(acc[mi][ni][1]),
                          "+f"(acc[mi][ni][2]), "+f"(acc[mi][ni][3])
                        : "r"(a_frag[mi][0]), "r"(a_frag[mi][1]),
                          "r"(a_frag[mi][2]), "r"(a_frag[mi][3]),
                          "r"(b0), "r"(b1));
                }
            }
        }
    }

    // Epilogue: acc -> g_h. Row = lane>>2 (+8), col pair = (lane&3)*2.
    #pragma unroll
    for (int mi = 0; mi < 2; mi++) {
        int r0 = brow + warp_m * 32 + mi * 16 + (lane >> 2);
        #pragma unroll
        for (int ni = 0; ni < 8; ni++) {
            int col = warp_n * 64 + ni * 8 + (lane & 3) * 2;
            if (r0 < M)
                *(float2*)(g_h + (size_t)r0 * DIM + col) =
                    make_float2(acc[mi][ni][0], acc[mi][ni][1]);
            if (r0 + 8 < M)
                *(float2*)(g_h + (size_t)(r0 + 8) * DIM + col) =
                    make_float2(acc[mi][ni][2], acc[mi][ni][3]);
        }
    }
}

// ------------------------- 4) per-node attention logits -------------------------
__global__ __launch_bounds__(256)
void attn_logits_kernel(const float* __restrict__ att_src,
                        const float* __restrict__ att_dst, int N)
{
    int g    = blockIdx.x * blockDim.x + threadIdx.x;
    int node = g >> 5;
    int lane = threadIdx.x & 31;
    if (node >= N) return;

    const float4* row = (const float4*)(g_h + (size_t)node * DIM);
    const float4* as4 = (const float4*)att_src;
    const float4* ad4 = (const float4*)att_dst;

    float4 h0 = row[lane],  h1 = row[lane + 32];
    float4 s0v = as4[lane], s1v = as4[lane + 32];
    float4 d0v = ad4[lane], d1v = ad4[lane + 32];

    float s0 = h0.x * s0v.x + h0.y * s0v.y + h0.z * s0v.z + h0.w * s0v.w;
    float d0 = h0.x * d0v.x + h0.y * d0v.y + h0.z * d0v.z + h0.w * d0v.w;
    float s1 = h1.x * s1v.x + h1.y * s1v.y + h1.z * s1v.z + h1.w * s1v.w;
    float d1 = h1.x * d1v.x + h1.y * d1v.y + h1.z * d1v.z + h1.w * d1v.w;

    #pragma unroll
    for (int off = 8; off; off >>= 1) {
        s0 += __shfl_down_sync(0xffffffffu, s0, off, 16);
        d0 += __shfl_down_sync(0xffffffffu, d0, off, 16);
        s1 += __shfl_down_sync(0xffffffffu, s1, off, 16);
        d1 += __shfl_down_sync(0xffffffffu, d1, off, 16);
    }
    if ((lane & 15) == 0) {
        int hgrp = lane >> 4;  // 0 or 1
        float* ap = (float*)&g_asrc[node];
        float* dp = (float*)&g_adst[node];
        ap[hgrp] = s0;  ap[hgrp + 2] = s1;
        dp[hgrp] = d0;  dp[hgrp + 2] = d1;
    }
}

// ------------------------- 5) edge logits + denom + deg -------------------------
__global__ __launch_bounds__(256)
void edge_logits_kernel(const int* __restrict__ ei32, int E, int T)
{
    int t = blockIdx.x * blockDim.x + threadIdx.x;
    if (t >= T) return;
    int stride = g_idx_stride;
    int s, d;
    if (t < E) load_edge(ei32, t, E, stride, s, d);
    else       s = d = t - E;

    float4 a = g_asrc[s];
    float4 b = g_adst[d];
    float4 e = make_float4(a.x + b.x, a.y + b.y, a.z + b.z, a.w + b.w);
    e.x = e.x > 0.f ? e.x : NEG_SLOPE * e.x;
    e.y = e.y > 0.f ? e.y : NEG_SLOPE * e.y;
    e.z = e.z > 0.f ? e.z : NEG_SLOPE * e.z;
    e.w = e.w > 0.f ? e.w : NEG_SLOPE * e.w;
    // max-shift unnecessary: |e| small, exp fp32-safe, shift cancels in num/denom
    float4 nm = make_float4(expf(e.x), expf(e.y), expf(e.z), expf(e.w));
    g_num[t] = nm;
    red_add_v4(&g_denom[d], nm);
    atomicAdd(&g_deg[d], 1);
}

// ------------------------- 6) CSR build: scan + fill -------------------------
__global__ void scan1_kernel(int N)
{
    __shared__ int sh[1024];
    int i = blockIdx.x * 1024 + threadIdx.x;
    int v = (i < N) ? g_deg[i] : 0;
    sh[threadIdx.x] = v;
    __syncthreads();
    #pragma unroll
    for (int off = 1; off < 1024; off <<= 1) {
        int t = (threadIdx.x >= off) ? sh[threadIdx.x - off] : 0;
        __syncthreads();
        sh[threadIdx.x] += t;
        __syncthreads();
    }
    if (i < N) g_rowoff[i] = sh[threadIdx.x] - v;   // exclusive within block
    if (threadIdx.x == 1023) g_bsum[blockIdx.x] = sh[1023];
}

__global__ void scan2_kernel(int nb)
{
    if (threadIdx.x == 0) {
        int run = 0;
        for (int b = 0; b < nb; b++) { g_bbase[b] = run; run += g_bsum[b]; }
    }
}

__global__ void scan3_kernel(int N)
{
    int i = blockIdx.x * blockDim.x + threadIdx.x;
    if (i < N) {
        int o = g_rowoff[i] + g_bbase[i >> 10];
        g_rowoff[i] = o;
        g_cursor[i] = o;
    }
}

__global__ void fill_kernel(const int* __restrict__ ei32, int E, int T)
{
    int t = blockIdx.x * blockDim.x + threadIdx.x;
    if (t >= T) return;
    int stride = g_idx_stride;
    int s, d;
    if (t < E) load_edge(ei32, t, E, stride, s, d);
    else       s = d = t - E;
    int pos = atomicAdd(&g_cursor[d], 1);
    g_slot[pos] = make_int2(s, t);
}

// ------------------------- 7) aggregate (warp/node) + bias + ReLU -------------
__global__ __launch_bounds__(256)
void aggregate_kernel(float* __restrict__ out, const float* __restrict__ bias, int N)
{
    int g    = blockIdx.x * blockDim.x + threadIdx.x;
    int node = g >> 5;
    int lane = threadIdx.x & 31;
    if (node >= N) return;

    int off = g_rowoff[node];
    int deg = g_deg[node];
    float4 dn  = g_denom[node];
    float4 inv = make_float4(1.f / dn.x, 1.f / dn.y, 1.f / dn.z, 1.f / dn.w);

    float4 a0 = make_float4(0.f, 0.f, 0.f, 0.f);
    float4 a1 = make_float4(0.f, 0.f, 0.f, 0.f);

    for (int e = 0; e < deg; e++) {
        int2 sl = g_slot[off + e];
        float4 nm = g_num[sl.y];
        float w01 = (lane < 16) ? nm.x * inv.x : nm.y * inv.y;  // heads 0/1
        float w23 = (lane < 16) ? nm.z * inv.z : nm.w * inv.w;  // heads 2/3
        const float4* hr = (const float4*)(g_h + (size_t)sl.x * DIM);
        float4 v0 = hr[lane];
        float4 v1 = hr[lane + 32];
        a0.x = fmaf(w01, v0.x, a0.x); a0.y = fmaf(w01, v0.y, a0.y);
        a0.z = fmaf(w01, v0.z, a0.z); a0.w = fmaf(w01, v0.w, a0.w);
        a1.x = fmaf(w23, v1.x, a1.x); a1.y = fmaf(w23, v1.y, a1.y);
        a1.z = fmaf(w23, v1.z, a1.z); a1.w = fmaf(w23, v1.w, a1.w);
    }

    const float4* b4 = (const float4*)bias;
    float4 bb0 = b4[lane], bb1 = b4[lane + 32];
    a0.x = fmaxf(a0.x + bb0.x, 0.f); a0.y = fmaxf(a0.y + bb0.y, 0.f);
    a0.z = fmaxf(a0.z + bb0.z, 0.f); a0.w = fmaxf(a0.w + bb0.w, 0.f);
    a1.x = fmaxf(a1.x + bb1.x, 0.f); a1.y = fmaxf(a1.y + bb1.y, 0.f);
    a1.z = fmaxf(a1.z + bb1.z, 0.f); a1.w = fmaxf(a1.w + bb1.w, 0.f);

    float4* orow = (float4*)(out + (size_t)node * DIM);
    orow[lane]      = a0;
    orow[lane + 32] = a1;
}

// ------------------------- launch -------------------------
extern "C" void kernel_launch(void* const* d_in, const int* in_sizes, int n_in,
                              void* d_out, int out_size)
{
    const float* x       = (const float*)d_in[0];
    const int*   ei32    = (const int*)d_in[1];
    const float* W       = (const float*)d_in[2];
    const float* att_src = (const float*)d_in[3];
    const float* att_dst = (const float*)d_in[4];
    const float* bias    = (const float*)d_in[5];

    int N = in_sizes[0] / DIM;   // 50000
    int E = in_sizes[1] / 2;     // 800000
    int T = E + N;
    float* out = (float*)d_out;

    // 0) edge index dtype
    detect_idx_kernel<<<1, 256>>>(ei32, E);

    // 1) bf16 splits of W^T and x
    prep_w_kernel<<<(DIM * DIM + 255) / 256, 256>>>(W);
    split_x_kernel<<<(N * DIM / 4 + 255) / 256, 256>>>(x, N * DIM / 4);

    // 2) zero denom/deg
    init2_kernel<<<(N + 255) / 256, 256>>>(N);

    // 3) tensor-core GEMM (mma.sync bf16x3)
    gemm_mma_kernel<<<(N + GBM - 1) / GBM, 256>>>(N);

    // 4) per-node attention logits
    attn_logits_kernel<<<(N * 32 + 255) / 256, 256>>>(att_src, att_dst, N);

    // 5) edge softmax numerators + denom + degree
    edge_logits_kernel<<<(T + 255) / 256, 256>>>(ei32, E, T);

    // 6) CSR build
    int nb = (N + 1023) / 1024;
    scan1_kernel<<<nb, 1024>>>(N);
    scan2_kernel<<<1, 32>>>(nb);
    scan3_kernel<<<(N + 255) / 256, 256>>>(N);
    fill_kernel<<<(T + 255) / 256, 256>>>(ei32, E, T);

    // 7) per-node aggregation + bias + ReLU
    aggregate_kernel<<<(N * 32 + 255) / 256, 256>>>(out, bias, N);
}

// round 11
// speedup vs baseline: 1.2654x; 1.2654x over previous
#include <cuda_runtime.h>
#include <cuda_bf16.h>
#include <cuda_fp16.h>
#include <cstdint>

// N=50000 nodes, E=800000 edges, IN_DIM=256, HEADS=4, HID=64 -> out 256.
#define MAXN 50000
#define MAXE 800000
#define MAXT (MAXE + MAXN)
#define DIM 256
#define NEG_SLOPE 0.2f

// ------------------------- device scratch -------------------------
__device__ __align__(16) __half g_hh[(size_t)MAXN * DIM];  // projected features fp16
__device__ __nv_bfloat16  g_xhi[(size_t)MAXN * DIM];   // x split hi
__device__ __nv_bfloat16  g_xlo[(size_t)MAXN * DIM];   // x split lo
__device__ __nv_bfloat16  g_wthi[DIM * DIM];           // W^T split hi: [n][k]
__device__ __nv_bfloat16  g_wtlo[DIM * DIM];
__device__ float4 g_asrc[MAXN];
__device__ float4 g_adst[MAXN];
__device__ float4 g_denom[MAXN];
__device__ float4 g_num[MAXT];
__device__ int    g_deg[MAXN];
__device__ int    g_rowoff[MAXN];
__device__ int    g_cursor[MAXN];
__device__ int2   g_slot[MAXT];        // {src, edge_id} binned by dst
__device__ int    g_bsum[64];
__device__ int    g_bbase[64];
__device__ int    g_idx_stride;        // 1 = int32 indices, 2 = int64 low word

// ------------------------- helpers -------------------------
__device__ __forceinline__ uint32_t smem_u32(const void* p) {
    uint32_t a;
    asm("{ .reg .u64 t; cvta.to.shared.u64 t, %1; cvt.u32.u64 %0, t; }"
        : "=r"(a) : "l"(p));
    return a;
}
__device__ __forceinline__ void red_add_v4(float4* addr, float4 v) {
    asm volatile("red.global.add.v4.f32 [%0], {%1,%2,%3,%4};"
                 :: "l"(addr), "f"(v.x), "f"(v.y), "f"(v.z), "f"(v.w) : "memory");
}

// ------------------------- 0) dtype detection -------------------------
// JAX default x64-off silently makes edge_index int32; detect via odd words.
__global__ void detect_idx_kernel(const int* __restrict__ ei32, int E)
{
    __shared__ int s_nonzero;
    if (threadIdx.x == 0) s_nonzero = 0;
    __syncthreads();
    int nz = 0;
    int samples = (E < 4096) ? E : 4096;
    for (int i = threadIdx.x; i < samples; i += blockDim.x)
        nz |= ei32[2 * i + 1];
    if (nz) atomicOr(&s_nonzero, 1);
    __syncthreads();
    if (threadIdx.x == 0) g_idx_stride = s_nonzero ? 1 : 2;
}

__device__ __forceinline__ void load_edge(const int* __restrict__ ei32,
                                          int t, int E, int stride, int& s, int& d)
{
    s = ei32[(size_t)t * stride];
    d = ei32[((size_t)E + t) * stride];
}

// ------------------------- 1a) W transpose + bf16 split -------------------------
__global__ void prep_w_kernel(const float* __restrict__ W)
{
    int i = blockIdx.x * blockDim.x + threadIdx.x;   // i = k*256 + n
    if (i < DIM * DIM) {
        int k = i >> 8, n = i & 255;
        float w = W[i];
        __nv_bfloat16 hi = __float2bfloat16(w);
        __nv_bfloat16 lo = __float2bfloat16(w - __bfloat162float(hi));
        g_wthi[n * DIM + k] = hi;
        g_wtlo[n * DIM + k] = lo;
    }
}

// ------------------------- 1b) x bf16 split (+ denom/deg init fused) ----------
__global__ void split_x_kernel(const float* __restrict__ x, int total4, int N)
{
    int i = blockIdx.x * blockDim.x + threadIdx.x;
    if (i < total4) {
        float4 v = ((const float4*)x)[i];
        __nv_bfloat16 h0 = __float2bfloat16(v.x), h1 = __float2bfloat16(v.y);
        __nv_bfloat16 h2 = __float2bfloat16(v.z), h3 = __float2bfloat16(v.w);
        __nv_bfloat16 l0 = __float2bfloat16(v.x - __bfloat162float(h0));
        __nv_bfloat16 l1 = __float2bfloat16(v.y - __bfloat162float(h1));
        __nv_bfloat16 l2 = __float2bfloat16(v.z - __bfloat162float(h2));
        __nv_bfloat16 l3 = __float2bfloat16(v.w - __bfloat162float(h3));
        ((__nv_bfloat162*)g_xhi)[2 * i]     = __halves2bfloat162(h0, h1);
        ((__nv_bfloat162*)g_xhi)[2 * i + 1] = __halves2bfloat162(h2, h3);
        ((__nv_bfloat162*)g_xlo)[2 * i]     = __halves2bfloat162(l0, l1);
        ((__nv_bfloat162*)g_xlo)[2 * i + 1] = __halves2bfloat162(l2, l3);
    }
    if (i < N) { g_denom[i] = make_float4(0.f, 0.f, 0.f, 0.f); g_deg[i] = 0; }
}

// ------------------------- 2) GEMM via mma.sync bf16x3 + fused logits ---------
// h = x@W with split: hi*hi + lo*hi + hi*lo, fp32 accumulate.
// (tcgen05 is compile-blocked: harness lowers via compute_103 PTX, no 'a' feat.)
// CTA tile 64(M) x 256(N), BK=64, 8 warps (2x4), warp tile 32x64.
// Epilogue: fp16 h store + per-row att_src/att_dst dots (head == warp_n).
#define GBM 64
#define GBK 64
#define ASTR 72   // bf16 stride with +8 pad -> ldmatrix conflict-free

__global__ __launch_bounds__(256)
void gemm_mma_kernel(const float* __restrict__ att_src,
                     const float* __restrict__ att_dst, int M)
{
    __shared__ __align__(16) __nv_bfloat16 As[GBM * ASTR];   //  9216 B
    __shared__ __align__(16) __nv_bfloat16 Bs[DIM * ASTR];   // 36864 B
    __shared__ float satts[DIM], sattd[DIM];

    int tid = threadIdx.x, lane = tid & 31, wid = tid >> 5;
    int warp_m = wid & 1;        // 0..1
    int warp_n = wid >> 1;       // 0..3  (== head index)
    int brow = blockIdx.x * GBM;

    satts[tid] = att_src[tid];
    sattd[tid] = att_dst[tid];

    float acc[2][8][4];
    #pragma unroll
    for (int mi = 0; mi < 2; mi++)
        #pragma unroll
        for (int ni = 0; ni < 8; ni++)
            #pragma unroll
            for (int q = 0; q < 4; q++) acc[mi][ni][q] = 0.f;

    uint32_t As_a = smem_u32(As);
    uint32_t Bs_a = smem_u32(Bs);

    // ldmatrix lane address components
    int a_row = warp_m * 32 + (lane & 15);              // + mi*16
    int a_k   = (lane >> 4) << 3;                       // 0/8, + ks*16
    // B x4: q = lane>>3 -> {n+0,k0},{n+0,k8},{n+8,k0},{n+8,k8}
    int b_row = warp_n * 64 + ((lane >> 4) & 1) * 8 + (lane & 7);  // + np*16
    int b_k   = ((lane >> 3) & 1) << 3;                 // + ks*16

    for (int it = 0; it < 12; it++) {
        int pass = it >> 2, kc = it & 3;
        const __nv_bfloat16* ap = (pass == 1) ? g_xlo  : g_xhi;
        const __nv_bfloat16* bp = (pass == 2) ? g_wtlo : g_wthi;

        __syncthreads();   // previous iter's reads done
        // A: 64 rows x 64 bf16 = 512 uint4, 2 per thread
        #pragma unroll
        for (int i = 0; i < 2; i++) {
            int idx = tid + i * 256;
            int r = idx >> 3, c = (idx & 7) << 3;
            uint4 v = make_uint4(0u, 0u, 0u, 0u);
            if (brow + r < M)
                v = *(const uint4*)(ap + (size_t)(brow + r) * DIM + kc * GBK + c);
            *(uint4*)&As[r * ASTR + c] = v;
        }
        // B: 256 rows x 64 bf16 = 2048 uint4, 8 per thread
        #pragma unroll
        for (int i = 0; i < 8; i++) {
            int idx = tid + i * 256;
            int r = idx >> 3, c = (idx & 7) << 3;
            uint4 v = *(const uint4*)(bp + (size_t)r * DIM + kc * GBK + c);
            *(uint4*)&Bs[r * ASTR + c] = v;
        }
        __syncthreads();

        #pragma unroll
        for (int ks = 0; ks < 4; ks++) {
            uint32_t a_frag[2][4];
            #pragma unroll
            for (int mi = 0; mi < 2; mi++) {
                uint32_t addr = As_a +
                    (uint32_t)(((a_row + mi * 16) * ASTR + ks * 16 + a_k) * 2);
                asm volatile(
                    "ldmatrix.sync.aligned.m8n8.x4.shared.b16 {%0,%1,%2,%3}, [%4];"
                    : "=r"(a_frag[mi][0]), "=r"(a_frag[mi][1]),
                      "=r"(a_frag[mi][2]), "=r"(a_frag[mi][3])
                    : "r"(addr));
            }
            #pragma unroll
            for (int np = 0; np < 4; np++) {   // ni pairs {2np, 2np+1}
                uint32_t b0, b1, b2, b3;
                uint32_t addr = Bs_a +
                    (uint32_t)(((b_row + np * 16) * ASTR + ks * 16 + b_k) * 2);
                asm volatile(
                    "ldmatrix.sync.aligned.m8n8.x4.shared.b16 {%0,%1,%2,%3}, [%4];"
                    : "=r"(b0), "=r"(b1), "=r"(b2), "=r"(b3) : "r"(addr));
                #pragma unroll
                for (int mi = 0; mi < 2; mi++) {
                    asm volatile(
                        "mma.sync.aligned.m16n8k16.row.col.f32.bf16.bf16.f32 "
                        "{%0,%1,%2,%3}, {%4,%5,%6,%7}, {%8,%9}, {%0,%1,%2,%3};"
                        : "+f"(acc[mi][2*np][0]), "+f"(acc[mi][2*np][1]),
                          "+f"(acc[mi][2*np][2]), "+f"(acc[mi][2*np][3])
                        : "r"(a_frag[mi][0]), "r"(a_frag[mi][1]),
                          "r"(a_frag[mi][2]), "r"(a_frag[mi][3]),
                          "r"(b0), "r"(b1));
                    asm volatile(
                        "mma.sync.aligned.m16n8k16.row.col.f32.bf16.bf16.f32 "
                        "{%0,%1,%2,%3}, {%4,%5,%6,%7}, {%8,%9}, {%0,%1,%2,%3};"
                        : "+f"(acc[mi][2*np+1][0]), "+f"(acc[mi][2*np+1][1]),
                          "+f"(acc[mi][2*np+1][2]), "+f"(acc[mi][2*np+1][3])
                        : "r"(a_frag[mi][0]), "r"(a_frag[mi][1]),
                          "r"(a_frag[mi][2]), "r"(a_frag[mi][3]),
                          "r"(b2), "r"(b3));
                }
            }
        }
    }

    // Epilogue: fp16 h store + fused per-head attention dots.
    // Thread covers rows r_lo=(warp_m*32+mi*16+lane>>2), r_hi=r_lo+8,
    // cols warp_n*64 + ni*8 + (lane&3)*2 (+1). Head == warp_n.
    #pragma unroll
    for (int mi = 0; mi < 2; mi++) {
        int r_lo = brow + warp_m * 32 + mi * 16 + (lane >> 2);
        int r_hi = r_lo + 8;
        float s_lo = 0.f, d_lo = 0.f, s_hi = 0.f, d_hi = 0.f;
        #pragma unroll
        for (int ni = 0; ni < 8; ni++) {
            int c0 = warp_n * 64 + ni * 8 + (lane & 3) * 2;
            float v0 = acc[mi][ni][0], v1 = acc[mi][ni][1];
            float v2 = acc[mi][ni][2], v3 = acc[mi][ni][3];
            if (r_lo < M)
                *(__half2*)(g_hh + (size_t)r_lo * DIM + c0) =
                    __float22half2_rn(make_float2(v0, v1));
            if (r_hi < M)
                *(__half2*)(g_hh + (size_t)r_hi * DIM + c0) =
                    __float22half2_rn(make_float2(v2, v3));
            float ts0 = satts[c0], ts1 = satts[c0 + 1];
            float td0 = sattd[c0], td1 = sattd[c0 + 1];
            s_lo += v0 * ts0 + v1 * ts1;
            d_lo += v0 * td0 + v1 * td1;
            s_hi += v2 * ts0 + v3 * ts1;
            d_hi += v2 * td0 + v3 * td1;
        }
        // reduce over lane&3 (4 threads share a row)
        #pragma unroll
        for (int off = 1; off <= 2; off <<= 1) {
            s_lo += __shfl_xor_sync(0xffffffffu, s_lo, off);
            d_lo += __shfl_xor_sync(0xffffffffu, d_lo, off);
            s_hi += __shfl_xor_sync(0xffffffffu, s_hi, off);
            d_hi += __shfl_xor_sync(0xffffffffu, d_hi, off);
        }
        if ((lane & 3) == 0) {
            if (r_lo < M) {
                ((float*)&g_asrc[r_lo])[warp_n] = s_lo;
                ((float*)&g_adst[r_lo])[warp_n] = d_lo;
            }
            if (r_hi < M) {
                ((float*)&g_asrc[r_hi])[warp_n] = s_hi;
                ((float*)&g_adst[r_hi])[warp_n] = d_hi;
            }
        }
    }
}

// ------------------------- 3) edge logits + denom + deg -------------------------
__global__ __launch_bounds__(256)
void edge_logits_kernel(const int* __restrict__ ei32, int E, int T)
{
    int t = blockIdx.x * blockDim.x + threadIdx.x;
    if (t >= T) return;
    int stride = g_idx_stride;
    int s, d;
    if (t < E) load_edge(ei32, t, E, stride, s, d);
    else       s = d = t - E;

    float4 a = g_asrc[s];
    float4 b = g_adst[d];
    float4 e = make_float4(a.x + b.x, a.y + b.y, a.z + b.z, a.w + b.w);
    e.x = e.x > 0.f ? e.x : NEG_SLOPE * e.x;
    e.y = e.y > 0.f ? e.y : NEG_SLOPE * e.y;
    e.z = e.z > 0.f ? e.z : NEG_SLOPE * e.z;
    e.w = e.w > 0.f ? e.w : NEG_SLOPE * e.w;
    // max-shift unnecessary: |e| small, exp fp32-safe, shift cancels in num/denom
    float4 nm = make_float4(expf(e.x), expf(e.y), expf(e.z), expf(e.w));
    g_num[t] = nm;
    red_add_v4(&g_denom[d], nm);
    atomicAdd(&g_deg[d], 1);
}

// ------------------------- 4) CSR build: scan + fill -------------------------
__global__ void scan1_kernel(int N)
{
    __shared__ int sh[1024];
    int i = blockIdx.x * 1024 + threadIdx.x;
    int v = (i < N) ? g_deg[i] : 0;
    sh[threadIdx.x] = v;
    __syncthreads();
    #pragma unroll
    for (int off = 1; off < 1024; off <<= 1) {
        int t = (threadIdx.x >= off) ? sh[threadIdx.x - off] : 0;
        __syncthreads();
        sh[threadIdx.x] += t;
        __syncthreads();
    }
    if (i < N) g_rowoff[i] = sh[threadIdx.x] - v;   // exclusive within block
    if (threadIdx.x == 1023) g_bsum[blockIdx.x] = sh[1023];
}

__global__ void scan2_kernel(int nb)
{
    if (threadIdx.x == 0) {
        int run = 0;
        for (int b = 0; b < nb; b++) { g_bbase[b] = run; run += g_bsum[b]; }
    }
}

__global__ void scan3_kernel(int N)
{
    int i = blockIdx.x * blockDim.x + threadIdx.x;
    if (i < N) {
        int o = g_rowoff[i] + g_bbase[i >> 10];
        g_rowoff[i] = o;
        g_cursor[i] = o;
    }
}

__global__ void fill_kernel(const int* __restrict__ ei32, int E, int T)
{
    int t = blockIdx.x * blockDim.x + threadIdx.x;
    if (t >= T) return;
    int stride = g_idx_stride;
    int s, d;
    if (t < E) load_edge(ei32, t, E, stride, s, d);
    else       s = d = t - E;
    int pos = atomicAdd(&g_cursor[d], 1);
    g_slot[pos] = make_int2(s, t);
}

// ------------------------- 5) aggregate (warp/node) + bias + ReLU -------------
// Lane covers halves [8*lane, 8*lane+8) of the 256-wide row -> head = lane>>3.
__global__ __launch_bounds__(256)
void aggregate_kernel(float* __restrict__ out, const float* __restrict__ bias, int N)
{
    int g    = blockIdx.x * blockDim.x + threadIdx.x;
    int node = g >> 5;
    int lane = threadIdx.x & 31;
    if (node >= N) return;

    int off = g_rowoff[node];
    int deg = g_deg[node];
    int head = lane >> 3;
    float4 dn = g_denom[node];
    float dh = (head == 0) ? dn.x : (head == 1) ? dn.y : (head == 2) ? dn.z : dn.w;
    float inv = 1.f / dh;

    float a0 = 0.f, a1 = 0.f, a2 = 0.f, a3 = 0.f;
    float a4 = 0.f, a5 = 0.f, a6 = 0.f, a7 = 0.f;

    const uint4* hbase = (const uint4*)g_hh;   // 32 uint4 (512B) per row
    for (int e = 0; e < deg; e++) {
        int2 sl = g_slot[off + e];
        float4 nm = g_num[sl.y];
        float nh = (head == 0) ? nm.x : (head == 1) ? nm.y : (head == 2) ? nm.z : nm.w;
        float w = nh * inv;
        uint4 v = hbase[(size_t)sl.x * 32 + lane];   // 8 halves
        float2 f0 = __half22float2(*(__half2*)&v.x);
        float2 f1 = __half22float2(*(__half2*)&v.y);
        float2 f2 = __half22float2(*(__half2*)&v.z);
        float2 f3 = __half22float2(*(__half2*)&v.w);
        a0 = fmaf(w, f0.x, a0); a1 = fmaf(w, f0.y, a1);
        a2 = fmaf(w, f1.x, a2); a3 = fmaf(w, f1.y, a3);
        a4 = fmaf(w, f2.x, a4); a5 = fmaf(w, f2.y, a5);
        a6 = fmaf(w, f3.x, a6); a7 = fmaf(w, f3.y, a7);
    }

    const float4* b4 = (const float4*)bias;
    float4 bb0 = b4[2 * lane], bb1 = b4[2 * lane + 1];
    float4 o0 = make_float4(fmaxf(a0 + bb0.x, 0.f), fmaxf(a1 + bb0.y, 0.f),
                            fmaxf(a2 + bb0.z, 0.f), fmaxf(a3 + bb0.w, 0.f));
    float4 o1 = make_float4(fmaxf(a4 + bb1.x, 0.f), fmaxf(a5 + bb1.y, 0.f),
                            fmaxf(a6 + bb1.z, 0.f), fmaxf(a7 + bb1.w, 0.f));

    float4* orow = (float4*)(out + (size_t)node * DIM);
    orow[2 * lane]     = o0;
    orow[2 * lane + 1] = o1;
}

// ------------------------- launch -------------------------
extern "C" void kernel_launch(void* const* d_in, const int* in_sizes, int n_in,
                              void* d_out, int out_size)
{
    const float* x       = (const float*)d_in[0];
    const int*   ei32    = (const int*)d_in[1];
    const float* W       = (const float*)d_in[2];
    const float* att_src = (const float*)d_in[3];
    const float* att_dst = (const float*)d_in[4];
    const float* bias    = (const float*)d_in[5];

    int N = in_sizes[0] / DIM;   // 50000
    int E = in_sizes[1] / 2;     // 800000
    int T = E + N;
    float* out = (float*)d_out;

    // 0) edge index dtype
    detect_idx_kernel<<<1, 256>>>(ei32, E);

    // 1) bf16 splits of W^T and x (+ denom/deg zero)
    prep_w_kernel<<<(DIM * DIM + 255) / 256, 256>>>(W);
    split_x_kernel<<<(N * DIM / 4 + 255) / 256, 256>>>(x, N * DIM / 4, N);

    // 2) tensor-core GEMM (mma.sync bf16x3) + fused attn logits + fp16 h
    gemm_mma_kernel<<<(N + GBM - 1) / GBM, 256>>>(att_src, att_dst, N);

    // 3) edge softmax numerators + denom + degree
    edge_logits_kernel<<<(T + 255) / 256, 256>>>(ei32, E, T);

    // 4) CSR build
    int nb = (N + 1023) / 1024;
    scan1_kernel<<<nb, 1024>>>(N);
    scan2_kernel<<<1, 32>>>(nb);
    scan3_kernel<<<(N + 255) / 256, 256>>>(N);
    fill_kernel<<<(T + 255) / 256, 256>>>(ei32, E, T);

    // 5) per-node aggregation + bias + ReLU
    aggregate_kernel<<<(N * 32 + 255) / 256, 256>>>(out, bias, N);
}